// round 3
// baseline (speedup 1.0000x reference)
#include <cuda_runtime.h>
#include <math.h>

#define DIM   1024
#define T_TOK 16384
#define NL    3
#define NEXP  4
#define RRANK 16
#define LN_EPS 1e-5f

// ---------------- scratch (no allocations allowed) ----------------
__device__ float g_bufS[(size_t)T_TOK * DIM];  // liquid state S
__device__ float g_bufY[(size_t)T_TOK * DIM];  // pre-LN Y
__device__ float g_bufA[(size_t)T_TOK * DIM];  // post-LN activation / z_context

// ---------------- fused GEMM: C = epilogue(A @ W) ----------------
// MODE 0: out = sigmoid(acc + bias[c]) * cur[r,c] * td[c]      (liquid gate)
// MODE 1: out = acc + bias[c] + cur[r,c]                        (proj + residual)
#define BM 128
#define BN 128
#define BK 8
#define TM 8
#define TN 8

template <int MODE>
__global__ __launch_bounds__(256, 2)
void gemm_epi(const float* __restrict__ A, const float* __restrict__ W,
              const float* __restrict__ bias, const float* __restrict__ cur,
              const float* __restrict__ td, float* __restrict__ out)
{
    __shared__ float As[BK * BM];  // transposed A tile
    __shared__ float Bs[BK * BN];

    const int tid  = threadIdx.x;
    const int mTile = blockIdx.y;
    const int nTile = blockIdx.x;
    const int trow = tid / (BN / TN);   // 0..15
    const int tcol = tid % (BN / TN);   // 0..15

    const float* Ab = A + (size_t)mTile * BM * DIM;
    const float* Wb = W + (size_t)nTile * BN;

    const int aRow = tid >> 1;          // 0..127
    const int aCol = (tid & 1) * 4;     // 0 or 4
    const int bRow = tid >> 5;          // 0..7
    const int bCol = (tid & 31) * 4;    // 0..124

    float acc[TM][TN];
#pragma unroll
    for (int i = 0; i < TM; ++i)
#pragma unroll
        for (int j = 0; j < TN; ++j) acc[i][j] = 0.f;

    // prologue: tile 0
    float4 aReg = *(const float4*)(Ab + (size_t)aRow * DIM + aCol);
    float4 bReg = *(const float4*)(Wb + (size_t)bRow * DIM + bCol);
    As[(aCol + 0) * BM + aRow] = aReg.x;
    As[(aCol + 1) * BM + aRow] = aReg.y;
    As[(aCol + 2) * BM + aRow] = aReg.z;
    As[(aCol + 3) * BM + aRow] = aReg.w;
    *(float4*)(Bs + bRow * BN + bCol) = bReg;

    for (int k0 = 0; k0 < DIM; k0 += BK) {
        __syncthreads();
        const bool more = (k0 + BK) < DIM;
        if (more) {
            aReg = *(const float4*)(Ab + (size_t)aRow * DIM + (k0 + BK) + aCol);
            bReg = *(const float4*)(Wb + (size_t)(k0 + BK + bRow) * DIM + bCol);
        }
#pragma unroll
        for (int k = 0; k < BK; ++k) {
            float4 m0 = *(const float4*)(&As[k * BM + trow * TM]);
            float4 m1 = *(const float4*)(&As[k * BM + trow * TM + 4]);
            float4 n0 = *(const float4*)(&Bs[k * BN + tcol * TN]);
            float4 n1 = *(const float4*)(&Bs[k * BN + tcol * TN + 4]);
            float rm[TM] = {m0.x, m0.y, m0.z, m0.w, m1.x, m1.y, m1.z, m1.w};
            float rn[TN] = {n0.x, n0.y, n0.z, n0.w, n1.x, n1.y, n1.z, n1.w};
#pragma unroll
            for (int i = 0; i < TM; ++i)
#pragma unroll
                for (int j = 0; j < TN; ++j)
                    acc[i][j] = fmaf(rm[i], rn[j], acc[i][j]);
        }
        __syncthreads();
        if (more) {
            As[(aCol + 0) * BM + aRow] = aReg.x;
            As[(aCol + 1) * BM + aRow] = aReg.y;
            As[(aCol + 2) * BM + aRow] = aReg.z;
            As[(aCol + 3) * BM + aRow] = aReg.w;
            *(float4*)(Bs + bRow * BN + bCol) = bReg;
        }
    }

    // epilogue
#pragma unroll
    for (int i = 0; i < TM; ++i) {
        const size_t r = (size_t)mTile * BM + trow * TM + i;
#pragma unroll
        for (int jv = 0; jv < TN; jv += 4) {
            const int c = nTile * BN + tcol * TN + jv;
            float4 cv = *(const float4*)(cur + r * DIM + c);
            float4 b4 = *(const float4*)(bias + c);
            float4 o;
            if (MODE == 0) {
                float4 t4 = *(const float4*)(td + c);
                float v0 = acc[i][jv + 0] + b4.x;
                float v1 = acc[i][jv + 1] + b4.y;
                float v2 = acc[i][jv + 2] + b4.z;
                float v3 = acc[i][jv + 3] + b4.w;
                o.x = (1.f / (1.f + expf(-v0))) * cv.x * t4.x;
                o.y = (1.f / (1.f + expf(-v1))) * cv.y * t4.y;
                o.z = (1.f / (1.f + expf(-v2))) * cv.z * t4.z;
                o.w = (1.f / (1.f + expf(-v3))) * cv.w * t4.w;
            } else {
                o.x = acc[i][jv + 0] + b4.x + cv.x;
                o.y = acc[i][jv + 1] + b4.y + cv.y;
                o.z = acc[i][jv + 2] + b4.z + cv.z;
                o.w = acc[i][jv + 3] + b4.w + cv.w;
            }
            *(float4*)(out + r * DIM + c) = o;
        }
    }
}

// ---------------- LayerNorm over last dim (row = token) ----------------
__global__ __launch_bounds__(256)
void ln_kernel(const float* __restrict__ Y, const float* __restrict__ g,
               const float* __restrict__ beta, float* __restrict__ out)
{
    const size_t row = blockIdx.x;
    const int tid = threadIdx.x;
    float4 v = ((const float4*)(Y + row * DIM))[tid];

    float s = v.x + v.y + v.z + v.w;
    float q = fmaf(v.x, v.x, fmaf(v.y, v.y, fmaf(v.z, v.z, v.w * v.w)));
#pragma unroll
    for (int off = 16; off; off >>= 1) {
        s += __shfl_xor_sync(0xffffffffu, s, off);
        q += __shfl_xor_sync(0xffffffffu, q, off);
    }
    __shared__ float ss[8], qq[8], mv[2];
    if ((tid & 31) == 0) { ss[tid >> 5] = s; qq[tid >> 5] = q; }
    __syncthreads();
    if (tid == 0) {
        float S = 0.f, Q = 0.f;
#pragma unroll
        for (int w = 0; w < 8; ++w) { S += ss[w]; Q += qq[w]; }
        float mean = S * (1.0f / DIM);
        float var  = Q * (1.0f / DIM) - mean * mean;
        mv[0] = mean;
        mv[1] = rsqrtf(var + LN_EPS);
    }
    __syncthreads();
    const float mean = mv[0], rstd = mv[1];
    float4 g4 = ((const float4*)g)[tid];
    float4 b4 = ((const float4*)beta)[tid];
    float4 o;
    o.x = (v.x - mean) * rstd * g4.x + b4.x;
    o.y = (v.y - mean) * rstd * g4.y + b4.y;
    o.z = (v.z - mean) * rstd * g4.z + b4.z;
    o.w = (v.w - mean) * rstd * g4.w + b4.w;
    ((float4*)(out + row * DIM))[tid] = o;
}

// ---------------- MoLE: gate + top2 + LoRA experts, one block per token ----------------
__device__ __forceinline__ float gelu_exact(float x)
{
    return 0.5f * x * (1.f + erff(x * 0.70710678118654752440f));
}

__global__ __launch_bounds__(128)
void mole_kernel(const float* __restrict__ Z, const float* __restrict__ gate_W,
                 const float* __restrict__ gate_b, const float* __restrict__ lora_A,
                 const float* __restrict__ lora_B, float* __restrict__ pred,
                 float* __restrict__ gp)
{
    const size_t t = blockIdx.x;
    const int tid = threadIdx.x;
    const int lane = tid & 31, wid = tid >> 5;

    __shared__ float xs[DIM];
    __shared__ float lred[4][4];
    __shared__ float hred[4][32];
    __shared__ float hs[32];
    __shared__ int   eidx[2];

    // load token row
    ((float4*)xs)[tid]       = ((const float4*)(Z + t * DIM))[tid];
    ((float4*)xs)[tid + 128] = ((const float4*)(Z + t * DIM))[tid + 128];
    __syncthreads();

    // ---- gate logits (E=4 contiguous per row of gate_W) ----
    float4 la = {0.f, 0.f, 0.f, 0.f};
    for (int d = tid; d < DIM; d += 128) {
        float xv = xs[d];
        float4 w = *(const float4*)(gate_W + d * NEXP);
        la.x = fmaf(xv, w.x, la.x);
        la.y = fmaf(xv, w.y, la.y);
        la.z = fmaf(xv, w.z, la.z);
        la.w = fmaf(xv, w.w, la.w);
    }
#pragma unroll
    for (int off = 16; off; off >>= 1) {
        la.x += __shfl_xor_sync(0xffffffffu, la.x, off);
        la.y += __shfl_xor_sync(0xffffffffu, la.y, off);
        la.z += __shfl_xor_sync(0xffffffffu, la.z, off);
        la.w += __shfl_xor_sync(0xffffffffu, la.w, off);
    }
    if (lane == 0) {
        lred[wid][0] = la.x; lred[wid][1] = la.y;
        lred[wid][2] = la.z; lred[wid][3] = la.w;
    }
    __syncthreads();

    if (tid == 0) {
        float lg[NEXP];
#pragma unroll
        for (int e = 0; e < NEXP; ++e)
            lg[e] = lred[0][e] + lred[1][e] + lred[2][e] + lred[3][e] + gate_b[e];
        float m = lg[0];
#pragma unroll
        for (int e = 1; e < NEXP; ++e) m = fmaxf(m, lg[e]);
        float p[NEXP], s = 0.f;
#pragma unroll
        for (int e = 0; e < NEXP; ++e) { p[e] = expf(lg[e] - m); s += p[e]; }
        float inv = 1.f / s;
#pragma unroll
        for (int e = 0; e < NEXP; ++e) gp[t * NEXP + e] = p[e] * inv;
        // top-2 with lowest-index tie-break (matches jax top_k)
        int i0 = 0;
#pragma unroll
        for (int e = 1; e < NEXP; ++e) if (lg[e] > lg[i0]) i0 = e;
        int i1 = -1;
#pragma unroll
        for (int e = 0; e < NEXP; ++e)
            if (e != i0 && (i1 < 0 || lg[e] > lg[i1])) i1 = e;
        eidx[0] = i0; eidx[1] = i1;
    }
    __syncthreads();

    const int e0 = eidx[0], e1 = eidx[1];
    const float* A0 = lora_A + (size_t)e0 * DIM * RRANK;
    const float* A1 = lora_A + (size_t)e1 * DIM * RRANK;

    // ---- h[s][r] = sum_d x[d] * A[e_s][d][r] ----
    float hacc[32];
#pragma unroll
    for (int i = 0; i < 32; ++i) hacc[i] = 0.f;
    for (int d = tid; d < DIM; d += 128) {
        float xv = xs[d];
        const float4* a0 = (const float4*)(A0 + d * RRANK);
        const float4* a1 = (const float4*)(A1 + d * RRANK);
#pragma unroll
        for (int q = 0; q < 4; ++q) {
            float4 a = a0[q];
            hacc[q * 4 + 0] = fmaf(xv, a.x, hacc[q * 4 + 0]);
            hacc[q * 4 + 1] = fmaf(xv, a.y, hacc[q * 4 + 1]);
            hacc[q * 4 + 2] = fmaf(xv, a.z, hacc[q * 4 + 2]);
            hacc[q * 4 + 3] = fmaf(xv, a.w, hacc[q * 4 + 3]);
        }
#pragma unroll
        for (int q = 0; q < 4; ++q) {
            float4 a = a1[q];
            hacc[16 + q * 4 + 0] = fmaf(xv, a.x, hacc[16 + q * 4 + 0]);
            hacc[16 + q * 4 + 1] = fmaf(xv, a.y, hacc[16 + q * 4 + 1]);
            hacc[16 + q * 4 + 2] = fmaf(xv, a.z, hacc[16 + q * 4 + 2]);
            hacc[16 + q * 4 + 3] = fmaf(xv, a.w, hacc[16 + q * 4 + 3]);
        }
    }
#pragma unroll
    for (int off = 16; off; off >>= 1)
#pragma unroll
        for (int i = 0; i < 32; ++i)
            hacc[i] += __shfl_xor_sync(0xffffffffu, hacc[i], off);
    if (lane == 0)
#pragma unroll
        for (int i = 0; i < 32; ++i) hred[wid][i] = hacc[i];
    __syncthreads();
    if (tid < 32) {
        float v = hred[0][tid] + hred[1][tid] + hred[2][tid] + hred[3][tid];
        hs[tid] = gelu_exact(v);
    }
    __syncthreads();

    // ---- out[d] = sum_s sum_r h[s][r] * B[e_s][r][d] ----
    const float* B0 = lora_B + (size_t)e0 * RRANK * DIM;
    const float* B1 = lora_B + (size_t)e1 * RRANK * DIM;
#pragma unroll
    for (int i = 0; i < 8; ++i) {
        const int d = tid + i * 128;
        float acc = 0.f;
#pragma unroll
        for (int r = 0; r < RRANK; ++r) {
            acc = fmaf(hs[r],      B0[r * DIM + d], acc);
            acc = fmaf(hs[16 + r], B1[r * DIM + d], acc);
        }
        pred[t * DIM + d] = acc;
    }
}

// ---------------- host orchestration ----------------
static void run_stack(const float* x, const float* Wi, const float* bi, const float* td,
                      const float* Wo, const float* bo, const float* g, const float* beta,
                      float* bufS, float* bufY, float* bufA, float* finalOut)
{
    dim3 grid(DIM / BN, T_TOK / BM);
    const float* cur = x;
    for (int l = 0; l < NL; ++l) {
        gemm_epi<0><<<grid, 256>>>(cur, Wi + (size_t)l * DIM * DIM, bi + l * DIM,
                                   cur, td + l * DIM, bufS);
        gemm_epi<1><<<grid, 256>>>(bufS, Wo + (size_t)l * DIM * DIM, bo + l * DIM,
                                   cur, nullptr, bufY);
        float* lnout = (l == NL - 1) ? finalOut : bufA;
        ln_kernel<<<T_TOK, 256>>>(bufY, g + l * DIM, beta + l * DIM, lnout);
        cur = bufA;
    }
}

extern "C" void kernel_launch(void* const* d_in, const int* in_sizes, int n_in,
                              void* d_out, int out_size)
{
    const float* x_context = (const float*)d_in[0];
    const float* x_target  = (const float*)d_in[1];
    const float* enc_Wi   = (const float*)d_in[2];
    const float* enc_bi   = (const float*)d_in[3];
    const float* enc_td   = (const float*)d_in[4];
    const float* enc_Wo   = (const float*)d_in[5];
    const float* enc_bo   = (const float*)d_in[6];
    const float* enc_g    = (const float*)d_in[7];
    const float* enc_beta = (const float*)d_in[8];
    const float* tgt_Wi   = (const float*)d_in[9];
    const float* tgt_bi   = (const float*)d_in[10];
    const float* tgt_td   = (const float*)d_in[11];
    const float* tgt_Wo   = (const float*)d_in[12];
    const float* tgt_bo   = (const float*)d_in[13];
    const float* tgt_g    = (const float*)d_in[14];
    const float* tgt_beta = (const float*)d_in[15];
    const float* gate_W   = (const float*)d_in[16];
    const float* gate_b   = (const float*)d_in[17];
    const float* lora_A   = (const float*)d_in[18];
    const float* lora_B   = (const float*)d_in[19];

    float *bufS, *bufY, *bufA;
    cudaGetSymbolAddress((void**)&bufS, g_bufS);
    cudaGetSymbolAddress((void**)&bufY, g_bufY);
    cudaGetSymbolAddress((void**)&bufA, g_bufA);

    float* out  = (float*)d_out;
    float* pred = out;                                   // [T, D]
    float* gp   = out + (size_t)T_TOK * DIM;             // [T, E]
    float* ztg  = gp + (size_t)T_TOK * NEXP;             // [T, D]

    // encoder stack -> z_context in bufA
    run_stack(x_context, enc_Wi, enc_bi, enc_td, enc_Wo, enc_bo, enc_g, enc_beta,
              bufS, bufY, bufA, bufA);

    // MoLE on z_context -> pred_z + gate_probs
    mole_kernel<<<T_TOK, 128>>>(bufA, gate_W, gate_b, lora_A, lora_B, pred, gp);

    // target stack -> z_target directly into d_out
    run_stack(x_target, tgt_Wi, tgt_bi, tgt_td, tgt_Wo, tgt_bo, tgt_g, tgt_beta,
              bufS, bufY, bufA, ztg);
}

// round 9
// speedup vs baseline: 1.7672x; 1.7672x over previous
#include <cuda_runtime.h>
#include <cuda_bf16.h>
#include <math.h>
#include <stdint.h>

#define DIM   1024
#define T_TOK 16384
#define NL    3
#define NEXP  4
#define RRANK 16
#define LN_EPS 1e-5f

// ---------------- scratch (no allocations allowed) ----------------
__device__ float g_bufS[(size_t)T_TOK * DIM];  // liquid state S
__device__ float g_bufY[(size_t)T_TOK * DIM];  // pre-LN Y
__device__ float g_bufA[(size_t)T_TOK * DIM];  // post-LN activation / z_context
__device__ __nv_bfloat16 g_Whi[(size_t)DIM * DIM];  // W^T hi  [N][K]
__device__ __nv_bfloat16 g_Wlo[(size_t)DIM * DIM];  // W^T lo  [N][K]

// ================= PTX helpers (base compute_103 only!) =================
__device__ __forceinline__ uint32_t smem_u32(const void* p) {
    uint32_t a;
    asm("{ .reg .u64 t; cvta.to.shared.u64 t, %1; cvt.u32.u64 %0, t; }" : "=r"(a) : "l"(p));
    return a;
}

__device__ __forceinline__ void cp_async16(uint32_t dst, const void* src) {
    asm volatile("cp.async.cg.shared.global [%0], [%1], 16;" :: "r"(dst), "l"(src));
}
#define CP_COMMIT() asm volatile("cp.async.commit_group;" ::: "memory")
#define CP_WAIT0()  asm volatile("cp.async.wait_group 0;" ::: "memory")

__device__ __forceinline__ void ldsm_x4(uint32_t* r, uint32_t addr) {
    asm volatile("ldmatrix.sync.aligned.m8n8.x4.shared.b16 {%0,%1,%2,%3}, [%4];"
                 : "=r"(r[0]), "=r"(r[1]), "=r"(r[2]), "=r"(r[3]) : "r"(addr));
}

__device__ __forceinline__ void mma_bf16(float* d, const uint32_t* a, const uint32_t* b) {
    asm volatile(
        "mma.sync.aligned.m16n8k16.row.col.f32.bf16.bf16.f32 "
        "{%0,%1,%2,%3}, {%4,%5,%6,%7}, {%8,%9}, {%0,%1,%2,%3};"
        : "+f"(d[0]), "+f"(d[1]), "+f"(d[2]), "+f"(d[3])
        : "r"(a[0]), "r"(a[1]), "r"(a[2]), "r"(a[3]), "r"(b[0]), "r"(b[1]));
}

// split a float4 into packed-4 hi bf16 and packed-4 lo bf16 (8 bytes each)
__device__ __forceinline__ void split4(float4 v, unsigned long long& hi, unsigned long long& lo) {
    __nv_bfloat162 h0 = __float22bfloat162_rn(make_float2(v.x, v.y));
    __nv_bfloat162 h1 = __float22bfloat162_rn(make_float2(v.z, v.w));
    float2 f0 = __bfloat1622float2(h0);
    float2 f1 = __bfloat1622float2(h1);
    __nv_bfloat162 l0 = __float22bfloat162_rn(make_float2(v.x - f0.x, v.y - f0.y));
    __nv_bfloat162 l1 = __float22bfloat162_rn(make_float2(v.z - f1.x, v.w - f1.y));
    uint32_t uh0 = *reinterpret_cast<uint32_t*>(&h0);
    uint32_t uh1 = *reinterpret_cast<uint32_t*>(&h1);
    uint32_t ul0 = *reinterpret_cast<uint32_t*>(&l0);
    uint32_t ul1 = *reinterpret_cast<uint32_t*>(&l1);
    hi = (unsigned long long)uh0 | ((unsigned long long)uh1 << 32);
    lo = (unsigned long long)ul0 | ((unsigned long long)ul1 << 32);
}

// ---------------- W transpose + split: W[K][N] fp32 -> Whi/Wlo [N][K] bf16 ----------------
__global__ __launch_bounds__(256)
void wsplit_kernel(const float* __restrict__ W,
                   __nv_bfloat16* __restrict__ Whi, __nv_bfloat16* __restrict__ Wlo)
{
    __shared__ float tile[32][33];
    const int n0 = blockIdx.x * 32, k0 = blockIdx.y * 32;
    const int tx = threadIdx.x & 31, ty = threadIdx.x >> 5;
#pragma unroll
    for (int i = 0; i < 32; i += 8)
        tile[ty + i][tx] = W[(size_t)(k0 + ty + i) * DIM + n0 + tx];
    __syncthreads();
#pragma unroll
    for (int i = 0; i < 32; i += 8) {
        float v = tile[tx][ty + i];             // W[k0+tx][n0+ty+i]
        __nv_bfloat16 h = __float2bfloat16(v);
        const size_t o = (size_t)(n0 + ty + i) * DIM + k0 + tx;
        Whi[o] = h;
        Wlo[o] = __float2bfloat16(v - __bfloat162float(h));
    }
}

// ---------------- HMMA bf16x3 GEMM, fused epilogue ----------------
// MODE 0: out = sigmoid(acc + bias[c]) * cur[r,c] * td[c]
// MODE 1: out = acc + bias[c] + cur[r,c]
//
// CTA tile 128x128, BK=32, 8 warps (2 M x 4 N), warp tile 64x32.
// smem stage (32KB): Ah[128][32] @0, Al @8192, Bh[128n][32k] @16384, Bl @24576
// layout: byteoff(row, kh) = row*64 + (((kh>>3) ^ (row&3))<<4) + (kh&7)*2
#define BKC      32
#define NCH      (DIM / BKC)     // 32
#define STAGE_B  32768
#define SMEMSZ   (2 * STAGE_B)

template <int MODE>
__global__ __launch_bounds__(256, 1)
void gemm_mma(const float* __restrict__ A,
              const __nv_bfloat16* __restrict__ Whi, const __nv_bfloat16* __restrict__ Wlo,
              const float* __restrict__ bias, const float* __restrict__ cur,
              const float* __restrict__ td, float* __restrict__ out)
{
    extern __shared__ char smem[];
    const uint32_t sb = smem_u32(smem);
    const int tid  = threadIdx.x;
    const int wid  = tid >> 5, lane = tid & 31;
    const int mTile = blockIdx.y, nTile = blockIdx.x;
    const int wm = wid >> 2;      // 0..1
    const int wn = wid & 3;       // 0..3

    const float* Ab = A + (size_t)mTile * 128 * DIM;
    const __nv_bfloat16* BhG = Whi + (size_t)nTile * 128 * DIM;
    const __nv_bfloat16* BlG = Wlo + (size_t)nTile * 128 * DIM;

    // ---- fill-index decomposition ----
    // A: 1024 float4 per chunk: idx = tid + i*256; r = idx>>3, q = idx&7 (quad of 4 floats)
    const int aR = tid >> 3, aQ = tid & 7;
    // B: 512 x 16B per part per chunk: idx = tid + i*256; n = idx>>2, q = idx&3 (8-half group)
    const int bN = tid >> 2, bQ = tid & 3;

    float acc[4][4][4];
#pragma unroll
    for (int mt = 0; mt < 4; ++mt)
#pragma unroll
        for (int nt = 0; nt < 4; ++nt)
#pragma unroll
            for (int r = 0; r < 4; ++r) acc[mt][nt][r] = 0.f;

    // ---- helpers as lambdas ----
    auto storeA = [&](int stage, float4 v, int i) {
        const int r = aR + i * 32, q = aQ;
        unsigned long long hi, lo;
        split4(v, hi, lo);
        const uint32_t off = (uint32_t)(r * 64 + (((q >> 1) ^ (r & 3)) << 4) + (q & 1) * 8);
        *(unsigned long long*)(smem + stage * STAGE_B + off)        = hi;
        *(unsigned long long*)(smem + stage * STAGE_B + 8192 + off) = lo;
    };
    auto fillB = [&](int stage, int k0) {
#pragma unroll
        for (int i = 0; i < 2; ++i) {
            const int n = bN + i * 64, q = bQ;
            const uint32_t off = (uint32_t)(n * 64 + ((q ^ (n & 3)) << 4));
            cp_async16(sb + stage * STAGE_B + 16384 + off, BhG + (size_t)n * DIM + k0 + q * 8);
            cp_async16(sb + stage * STAGE_B + 24576 + off, BlG + (size_t)n * DIM + k0 + q * 8);
        }
    };

    // ---- prologue: chunk 0 direct fill; chunk 1 A prefetched to regs ----
    {
#pragma unroll
        for (int i = 0; i < 4; ++i) {
            float4 v = *(const float4*)(Ab + (size_t)(aR + i * 32) * DIM + aQ * 4);
            storeA(0, v, i);
        }
        fillB(0, 0);
        CP_COMMIT();
    }
    float4 pf[4];
#pragma unroll
    for (int i = 0; i < 4; ++i)
        pf[i] = *(const float4*)(Ab + (size_t)(aR + i * 32) * DIM + BKC + aQ * 4);

    const int l7 = lane & 7, l8 = (lane >> 3) & 1, l16 = lane >> 4;

    for (int c = 0; c < NCH; ++c) {
        const int s = c & 1;
        CP_WAIT0();
        __syncthreads();

        if (c + 1 < NCH) {
            const int s1 = (c + 1) & 1;
#pragma unroll
            for (int i = 0; i < 4; ++i) storeA(s1, pf[i], i);
            fillB(s1, (c + 1) * BKC);
            CP_COMMIT();
        }
        if (c + 2 < NCH) {
            const int k0 = (c + 2) * BKC;
#pragma unroll
            for (int i = 0; i < 4; ++i)
                pf[i] = *(const float4*)(Ab + (size_t)(aR + i * 32) * DIM + k0 + aQ * 4);
        }

        const uint32_t sA = sb + s * STAGE_B;
        const uint32_t sB = sA + 16384;
#pragma unroll
        for (int ks = 0; ks < 2; ++ks) {
            uint32_t a_hi[4][4], a_lo[4][4], b_hi[2][4], b_lo[2][4];
#pragma unroll
            for (int mt = 0; mt < 4; ++mt) {
                const int r = wm * 64 + mt * 16 + l8 * 8 + l7;
                const int ch = (ks * 2 + l16) ^ (r & 3);
                const uint32_t off = (uint32_t)(r * 64 + (ch << 4));
                ldsm_x4(a_hi[mt], sA + off);
                ldsm_x4(a_lo[mt], sA + 8192 + off);
            }
#pragma unroll
            for (int bt = 0; bt < 2; ++bt) {
                const int n = wn * 32 + bt * 16 + l16 * 8 + l7;
                const int ch = (ks * 2 + l8) ^ (n & 3);
                const uint32_t off = (uint32_t)(n * 64 + (ch << 4));
                ldsm_x4(b_hi[bt], sB + off);
                ldsm_x4(b_lo[bt], sB + 8192 + off);
            }
#pragma unroll
            for (int mt = 0; mt < 4; ++mt)
#pragma unroll
                for (int bt = 0; bt < 2; ++bt) {
                    mma_bf16(acc[mt][bt * 2 + 0], a_hi[mt], &b_hi[bt][0]);
                    mma_bf16(acc[mt][bt * 2 + 0], a_hi[mt], &b_lo[bt][0]);
                    mma_bf16(acc[mt][bt * 2 + 0], a_lo[mt], &b_hi[bt][0]);
                    mma_bf16(acc[mt][bt * 2 + 1], a_hi[mt], &b_hi[bt][2]);
                    mma_bf16(acc[mt][bt * 2 + 1], a_hi[mt], &b_lo[bt][2]);
                    mma_bf16(acc[mt][bt * 2 + 1], a_lo[mt], &b_hi[bt][2]);
                }
        }
        __syncthreads();
    }

    // ---- epilogue: acc registers -> fused output ----
    const int rq = lane >> 2;
    const int cq = (lane & 3) * 2;
#pragma unroll
    for (int mt = 0; mt < 4; ++mt) {
#pragma unroll
        for (int h = 0; h < 2; ++h) {
            const int row = mTile * 128 + wm * 64 + mt * 16 + h * 8 + rq;
            const float* curRow = cur + (size_t)row * DIM;
            float* outRow = out + (size_t)row * DIM;
#pragma unroll
            for (int nt = 0; nt < 4; ++nt) {
                const int col = nTile * 128 + wn * 32 + nt * 8 + cq;
                float v0 = acc[mt][nt][h * 2 + 0];
                float v1 = acc[mt][nt][h * 2 + 1];
                float2 b2 = *(const float2*)(bias + col);
                float2 c2 = *(const float2*)(curRow + col);
                float2 o;
                if (MODE == 0) {
                    float2 t2 = *(const float2*)(td + col);
                    float g0 = 1.f / (1.f + expf(-(v0 + b2.x)));
                    float g1 = 1.f / (1.f + expf(-(v1 + b2.y)));
                    o.x = g0 * c2.x * t2.x;
                    o.y = g1 * c2.y * t2.y;
                } else {
                    o.x = v0 + b2.x + c2.x;
                    o.y = v1 + b2.y + c2.y;
                }
                *(float2*)(outRow + col) = o;
            }
        }
    }
}

// ---------------- LayerNorm over last dim (row = token) ----------------
__global__ __launch_bounds__(256)
void ln_kernel(const float* __restrict__ Y, const float* __restrict__ g,
               const float* __restrict__ beta, float* __restrict__ out)
{
    const size_t row = blockIdx.x;
    const int tid = threadIdx.x;
    float4 v = ((const float4*)(Y + row * DIM))[tid];

    float s = v.x + v.y + v.z + v.w;
    float q = fmaf(v.x, v.x, fmaf(v.y, v.y, fmaf(v.z, v.z, v.w * v.w)));
#pragma unroll
    for (int off = 16; off; off >>= 1) {
        s += __shfl_xor_sync(0xffffffffu, s, off);
        q += __shfl_xor_sync(0xffffffffu, q, off);
    }
    __shared__ float ss[8], qq[8], mv[2];
    if ((tid & 31) == 0) { ss[tid >> 5] = s; qq[tid >> 5] = q; }
    __syncthreads();
    if (tid == 0) {
        float S = 0.f, Q = 0.f;
#pragma unroll
        for (int w = 0; w < 8; ++w) { S += ss[w]; Q += qq[w]; }
        float mean = S * (1.0f / DIM);
        float var  = Q * (1.0f / DIM) - mean * mean;
        mv[0] = mean;
        mv[1] = rsqrtf(var + LN_EPS);
    }
    __syncthreads();
    const float mean = mv[0], rstd = mv[1];
    float4 g4 = ((const float4*)g)[tid];
    float4 b4 = ((const float4*)beta)[tid];
    float4 o;
    o.x = (v.x - mean) * rstd * g4.x + b4.x;
    o.y = (v.y - mean) * rstd * g4.y + b4.y;
    o.z = (v.z - mean) * rstd * g4.z + b4.z;
    o.w = (v.w - mean) * rstd * g4.w + b4.w;
    ((float4*)(out + row * DIM))[tid] = o;
}

// ---------------- MoLE ----------------
__device__ __forceinline__ float gelu_exact(float x)
{
    return 0.5f * x * (1.f + erff(x * 0.70710678118654752440f));
}

__global__ __launch_bounds__(128)
void mole_kernel(const float* __restrict__ Z, const float* __restrict__ gate_W,
                 const float* __restrict__ gate_b, const float* __restrict__ lora_A,
                 const float* __restrict__ lora_B, float* __restrict__ pred,
                 float* __restrict__ gp)
{
    const size_t t = blockIdx.x;
    const int tid = threadIdx.x;
    const int lane = tid & 31, wid = tid >> 5;

    __shared__ float xs[DIM];
    __shared__ float lred[4][4];
    __shared__ float hred[4][32];
    __shared__ float hs[32];
    __shared__ int   eidx[2];

    ((float4*)xs)[tid]       = ((const float4*)(Z + t * DIM))[tid];
    ((float4*)xs)[tid + 128] = ((const float4*)(Z + t * DIM))[tid + 128];
    __syncthreads();

    float4 la = {0.f, 0.f, 0.f, 0.f};
    for (int d = tid; d < DIM; d += 128) {
        float xv = xs[d];
        float4 w = *(const float4*)(gate_W + d * NEXP);
        la.x = fmaf(xv, w.x, la.x);
        la.y = fmaf(xv, w.y, la.y);
        la.z = fmaf(xv, w.z, la.z);
        la.w = fmaf(xv, w.w, la.w);
    }
#pragma unroll
    for (int off = 16; off; off >>= 1) {
        la.x += __shfl_xor_sync(0xffffffffu, la.x, off);
        la.y += __shfl_xor_sync(0xffffffffu, la.y, off);
        la.z += __shfl_xor_sync(0xffffffffu, la.z, off);
        la.w += __shfl_xor_sync(0xffffffffu, la.w, off);
    }
    if (lane == 0) {
        lred[wid][0] = la.x; lred[wid][1] = la.y;
        lred[wid][2] = la.z; lred[wid][3] = la.w;
    }
    __syncthreads();

    if (tid == 0) {
        float lg[NEXP];
#pragma unroll
        for (int e = 0; e < NEXP; ++e)
            lg[e] = lred[0][e] + lred[1][e] + lred[2][e] + lred[3][e] + gate_b[e];
        float m = lg[0];
#pragma unroll
        for (int e = 1; e < NEXP; ++e) m = fmaxf(m, lg[e]);
        float p[NEXP], s = 0.f;
#pragma unroll
        for (int e = 0; e < NEXP; ++e) { p[e] = expf(lg[e] - m); s += p[e]; }
        float inv = 1.f / s;
#pragma unroll
        for (int e = 0; e < NEXP; ++e) gp[t * NEXP + e] = p[e] * inv;
        int i0 = 0;
#pragma unroll
        for (int e = 1; e < NEXP; ++e) if (lg[e] > lg[i0]) i0 = e;
        int i1 = -1;
#pragma unroll
        for (int e = 0; e < NEXP; ++e)
            if (e != i0 && (i1 < 0 || lg[e] > lg[i1])) i1 = e;
        eidx[0] = i0; eidx[1] = i1;
    }
    __syncthreads();

    const int e0 = eidx[0], e1 = eidx[1];
    const float* A0 = lora_A + (size_t)e0 * DIM * RRANK;
    const float* A1 = lora_A + (size_t)e1 * DIM * RRANK;

    float hacc[32];
#pragma unroll
    for (int i = 0; i < 32; ++i) hacc[i] = 0.f;
    for (int d = tid; d < DIM; d += 128) {
        float xv = xs[d];
        const float4* a0 = (const float4*)(A0 + d * RRANK);
        const float4* a1 = (const float4*)(A1 + d * RRANK);
#pragma unroll
        for (int q = 0; q < 4; ++q) {
            float4 a = a0[q];
            hacc[q * 4 + 0] = fmaf(xv, a.x, hacc[q * 4 + 0]);
            hacc[q * 4 + 1] = fmaf(xv, a.y, hacc[q * 4 + 1]);
            hacc[q * 4 + 2] = fmaf(xv, a.z, hacc[q * 4 + 2]);
            hacc[q * 4 + 3] = fmaf(xv, a.w, hacc[q * 4 + 3]);
        }
#pragma unroll
        for (int q = 0; q < 4; ++q) {
            float4 a = a1[q];
            hacc[16 + q * 4 + 0] = fmaf(xv, a.x, hacc[16 + q * 4 + 0]);
            hacc[16 + q * 4 + 1] = fmaf(xv, a.y, hacc[16 + q * 4 + 1]);
            hacc[16 + q * 4 + 2] = fmaf(xv, a.z, hacc[16 + q * 4 + 2]);
            hacc[16 + q * 4 + 3] = fmaf(xv, a.w, hacc[16 + q * 4 + 3]);
        }
    }
#pragma unroll
    for (int off = 16; off; off >>= 1)
#pragma unroll
        for (int i = 0; i < 32; ++i)
            hacc[i] += __shfl_xor_sync(0xffffffffu, hacc[i], off);
    if (lane == 0)
#pragma unroll
        for (int i = 0; i < 32; ++i) hred[wid][i] = hacc[i];
    __syncthreads();
    if (tid < 32) {
        float v = hred[0][tid] + hred[1][tid] + hred[2][tid] + hred[3][tid];
        hs[tid] = gelu_exact(v);
    }
    __syncthreads();

    const float* B0 = lora_B + (size_t)e0 * RRANK * DIM;
    const float* B1 = lora_B + (size_t)e1 * RRANK * DIM;
#pragma unroll
    for (int i = 0; i < 8; ++i) {
        const int d = tid + i * 128;
        float acc = 0.f;
#pragma unroll
        for (int r = 0; r < RRANK; ++r) {
            acc = fmaf(hs[r],      B0[r * DIM + d], acc);
            acc = fmaf(hs[16 + r], B1[r * DIM + d], acc);
        }
        pred[t * DIM + d] = acc;
    }
}

// ---------------- host orchestration ----------------
static void run_stack(const float* x, const float* Wi, const float* bi, const float* td,
                      const float* Wo, const float* bo, const float* g, const float* beta,
                      float* bufS, float* bufY, float* bufA, float* finalOut,
                      __nv_bfloat16* whi, __nv_bfloat16* wlo)
{
    dim3 ggrid(DIM / 128, T_TOK / 128);
    dim3 wgrid(DIM / 32, DIM / 32);
    const float* cur = x;
    for (int l = 0; l < NL; ++l) {
        wsplit_kernel<<<wgrid, 256>>>(Wi + (size_t)l * DIM * DIM, whi, wlo);
        gemm_mma<0><<<ggrid, 256, SMEMSZ>>>(cur, whi, wlo, bi + l * DIM,
                                            cur, td + l * DIM, bufS);
        wsplit_kernel<<<wgrid, 256>>>(Wo + (size_t)l * DIM * DIM, whi, wlo);
        gemm_mma<1><<<ggrid, 256, SMEMSZ>>>(bufS, whi, wlo, bo + l * DIM,
                                            cur, nullptr, bufY);
        float* lnout = (l == NL - 1) ? finalOut : bufA;
        ln_kernel<<<T_TOK, 256>>>(bufY, g + l * DIM, beta + l * DIM, lnout);
        cur = bufA;
    }
}

extern "C" void kernel_launch(void* const* d_in, const int* in_sizes, int n_in,
                              void* d_out, int out_size)
{
    const float* x_context = (const float*)d_in[0];
    const float* x_target  = (const float*)d_in[1];
    const float* enc_Wi   = (const float*)d_in[2];
    const float* enc_bi   = (const float*)d_in[3];
    const float* enc_td   = (const float*)d_in[4];
    const float* enc_Wo   = (const float*)d_in[5];
    const float* enc_bo   = (const float*)d_in[6];
    const float* enc_g    = (const float*)d_in[7];
    const float* enc_beta = (const float*)d_in[8];
    const float* tgt_Wi   = (const float*)d_in[9];
    const float* tgt_bi   = (const float*)d_in[10];
    const float* tgt_td   = (const float*)d_in[11];
    const float* tgt_Wo   = (const float*)d_in[12];
    const float* tgt_bo   = (const float*)d_in[13];
    const float* tgt_g    = (const float*)d_in[14];
    const float* tgt_beta = (const float*)d_in[15];
    const float* gate_W   = (const float*)d_in[16];
    const float* gate_b   = (const float*)d_in[17];
    const float* lora_A   = (const float*)d_in[18];
    const float* lora_B   = (const float*)d_in[19];

    float *bufS, *bufY, *bufA;
    __nv_bfloat16 *whi, *wlo;
    cudaGetSymbolAddress((void**)&bufS, g_bufS);
    cudaGetSymbolAddress((void**)&bufY, g_bufY);
    cudaGetSymbolAddress((void**)&bufA, g_bufA);
    cudaGetSymbolAddress((void**)&whi, g_Whi);
    cudaGetSymbolAddress((void**)&wlo, g_Wlo);

    static int attr_done = 0;
    if (!attr_done) {
        cudaFuncSetAttribute(gemm_mma<0>, cudaFuncAttributeMaxDynamicSharedMemorySize, SMEMSZ);
        cudaFuncSetAttribute(gemm_mma<1>, cudaFuncAttributeMaxDynamicSharedMemorySize, SMEMSZ);
        attr_done = 1;
    }

    float* out  = (float*)d_out;
    float* pred = out;                                   // [T, D]
    float* gp   = out + (size_t)T_TOK * DIM;             // [T, E]
    float* ztg  = gp + (size_t)T_TOK * NEXP;             // [T, D]

    // encoder stack -> z_context in bufA
    run_stack(x_context, enc_Wi, enc_bi, enc_td, enc_Wo, enc_bo, enc_g, enc_beta,
              bufS, bufY, bufA, bufA, whi, wlo);

    // MoLE on z_context -> pred_z + gate_probs
    mole_kernel<<<T_TOK, 128>>>(bufA, gate_W, gate_b, lora_A, lora_B, pred, gp);

    // target stack -> z_target directly into d_out
    run_stack(x_target, tgt_Wi, tgt_bi, tgt_td, tgt_Wo, tgt_bo, tgt_g, tgt_beta,
              bufS, bufY, bufA, ztg, whi, wlo);
}

// round 10
// speedup vs baseline: 2.3389x; 1.3235x over previous
#include <cuda_runtime.h>
#include <cuda_bf16.h>
#include <math.h>
#include <stdint.h>

#define DIM   1024
#define T_TOK 16384
#define NL    3
#define NEXP  4
#define RRANK 16
#define LN_EPS 1e-5f

// ---------------- scratch (no allocations allowed) ----------------
__device__ float g_bufY[(size_t)T_TOK * DIM];            // pre-LN Y (fp32)
__device__ float g_bufA[(size_t)T_TOK * DIM];            // post-LN activation (fp32)
__device__ __nv_bfloat16 g_Zhi[(size_t)T_TOK * DIM];     // split of gemm<0> A operand
__device__ __nv_bfloat16 g_Zlo[(size_t)T_TOK * DIM];
__device__ __nv_bfloat16 g_Shi[(size_t)T_TOK * DIM];     // split of liquid state S
__device__ __nv_bfloat16 g_Slo[(size_t)T_TOK * DIM];
__device__ __nv_bfloat16 g_Whi[(size_t)DIM * DIM];       // W^T hi  [N][K]
__device__ __nv_bfloat16 g_Wlo[(size_t)DIM * DIM];       // W^T lo  [N][K]

// ================= PTX helpers (base compute_103 only) =================
__device__ __forceinline__ uint32_t smem_u32(const void* p) {
    uint32_t a;
    asm("{ .reg .u64 t; cvta.to.shared.u64 t, %1; cvt.u32.u64 %0, t; }" : "=r"(a) : "l"(p));
    return a;
}

__device__ __forceinline__ void cp_async16(uint32_t dst, const void* src) {
    asm volatile("cp.async.cg.shared.global [%0], [%1], 16;" :: "r"(dst), "l"(src));
}
#define CP_COMMIT() asm volatile("cp.async.commit_group;" ::: "memory")
#define CP_WAIT0()  asm volatile("cp.async.wait_group 0;" ::: "memory")
#define CP_WAIT1()  asm volatile("cp.async.wait_group 1;" ::: "memory")

__device__ __forceinline__ void ldsm_x4(uint32_t* r, uint32_t addr) {
    asm volatile("ldmatrix.sync.aligned.m8n8.x4.shared.b16 {%0,%1,%2,%3}, [%4];"
                 : "=r"(r[0]), "=r"(r[1]), "=r"(r[2]), "=r"(r[3]) : "r"(addr));
}

__device__ __forceinline__ void mma_bf16(float* d, const uint32_t* a, const uint32_t* b) {
    asm volatile(
        "mma.sync.aligned.m16n8k16.row.col.f32.bf16.bf16.f32 "
        "{%0,%1,%2,%3}, {%4,%5,%6,%7}, {%8,%9}, {%0,%1,%2,%3};"
        : "+f"(d[0]), "+f"(d[1]), "+f"(d[2]), "+f"(d[3])
        : "r"(a[0]), "r"(a[1]), "r"(a[2]), "r"(a[3]), "r"(b[0]), "r"(b[1]));
}

// split a float4 into packed-4 hi bf16 and packed-4 lo bf16 (8 bytes each)
__device__ __forceinline__ void split4(float4 v, unsigned long long& hi, unsigned long long& lo) {
    __nv_bfloat162 h0 = __float22bfloat162_rn(make_float2(v.x, v.y));
    __nv_bfloat162 h1 = __float22bfloat162_rn(make_float2(v.z, v.w));
    float2 f0 = __bfloat1622float2(h0);
    float2 f1 = __bfloat1622float2(h1);
    __nv_bfloat162 l0 = __float22bfloat162_rn(make_float2(v.x - f0.x, v.y - f0.y));
    __nv_bfloat162 l1 = __float22bfloat162_rn(make_float2(v.z - f1.x, v.w - f1.y));
    uint32_t uh0 = *reinterpret_cast<uint32_t*>(&h0);
    uint32_t uh1 = *reinterpret_cast<uint32_t*>(&h1);
    uint32_t ul0 = *reinterpret_cast<uint32_t*>(&l0);
    uint32_t ul1 = *reinterpret_cast<uint32_t*>(&l1);
    hi = (unsigned long long)uh0 | ((unsigned long long)uh1 << 32);
    lo = (unsigned long long)ul0 | ((unsigned long long)ul1 << 32);
}

// split two fp32 -> one bf162 hi and one bf162 lo (as uint32)
__device__ __forceinline__ void split2(float a, float b, uint32_t& hi, uint32_t& lo) {
    __nv_bfloat162 h = __float22bfloat162_rn(make_float2(a, b));
    float2 f = __bfloat1622float2(h);
    __nv_bfloat162 l = __float22bfloat162_rn(make_float2(a - f.x, b - f.y));
    hi = *reinterpret_cast<uint32_t*>(&h);
    lo = *reinterpret_cast<uint32_t*>(&l);
}

// ---------------- x split: fp32 [T][D] -> hi/lo bf16 [T][D] ----------------
__global__ __launch_bounds__(256)
void xsplit_kernel(const float* __restrict__ X,
                   __nv_bfloat16* __restrict__ Xhi, __nv_bfloat16* __restrict__ Xlo)
{
    const size_t idx = (size_t)blockIdx.x * 256 + threadIdx.x;   // float4 index
    float4 v = ((const float4*)X)[idx];
    unsigned long long hi, lo;
    split4(v, hi, lo);
    ((unsigned long long*)Xhi)[idx] = hi;
    ((unsigned long long*)Xlo)[idx] = lo;
}

// ---------------- W transpose + split: W[K][N] fp32 -> Whi/Wlo [N][K] bf16 ----------------
__global__ __launch_bounds__(256)
void wsplit_kernel(const float* __restrict__ W,
                   __nv_bfloat16* __restrict__ Whi, __nv_bfloat16* __restrict__ Wlo)
{
    __shared__ float tile[32][33];
    const int n0 = blockIdx.x * 32, k0 = blockIdx.y * 32;
    const int tx = threadIdx.x & 31, ty = threadIdx.x >> 5;
#pragma unroll
    for (int i = 0; i < 32; i += 8)
        tile[ty + i][tx] = W[(size_t)(k0 + ty + i) * DIM + n0 + tx];
    __syncthreads();
#pragma unroll
    for (int i = 0; i < 32; i += 8) {
        float v = tile[tx][ty + i];             // W[k0+tx][n0+ty+i]
        __nv_bfloat16 h = __float2bfloat16(v);
        const size_t o = (size_t)(n0 + ty + i) * DIM + k0 + tx;
        Whi[o] = h;
        Wlo[o] = __float2bfloat16(v - __bfloat162float(h));
    }
}

// ---------------- HMMA bf16x3 GEMM, pure cp.async pipeline, fused epilogue ----------------
// A operand: pre-split bf16 [T][K] hi/lo.  B operand: pre-split W^T [N][K] hi/lo.
// MODE 0: s = sigmoid(acc + bias[c]) * cur[r,c] * td[c]  -> written as SPLIT bf16 (outHi/outLo)
// MODE 1: out = acc + bias[c] + cur[r,c]                 -> written fp32 (outF)
//
// CTA tile 128x128, BK=32, 8 warps (2M x 4N), warp tile 64x32, 3-stage cp.async pipeline.
// stage (32KB): Ah[128][32] @0, Al @8192, Bh[128n][32k] @16384, Bl @24576
// layout: byteoff(row, q16B) = row*64 + ((q ^ (row&3))<<4)
#define BKC      32
#define NCH      (DIM / BKC)     // 32
#define STAGE_B  32768
#define NSTAGE   3
#define SMEMSZ   (NSTAGE * STAGE_B)

template <int MODE>
__global__ __launch_bounds__(256, 2)
void gemm_mma(const __nv_bfloat16* __restrict__ Ahi, const __nv_bfloat16* __restrict__ Alo,
              const __nv_bfloat16* __restrict__ Whi, const __nv_bfloat16* __restrict__ Wlo,
              const float* __restrict__ bias, const float* __restrict__ cur,
              const float* __restrict__ td, float* __restrict__ outF,
              __nv_bfloat16* __restrict__ outHi, __nv_bfloat16* __restrict__ outLo)
{
    extern __shared__ char smem[];
    const uint32_t sb = smem_u32(smem);
    const int tid  = threadIdx.x;
    const int wid  = tid >> 5, lane = tid & 31;
    const int mTile = blockIdx.y, nTile = blockIdx.x;
    const int wm = wid >> 2;      // 0..1
    const int wn = wid & 3;       // 0..3

    const __nv_bfloat16* AhG = Ahi + (size_t)mTile * 128 * DIM;
    const __nv_bfloat16* AlG = Alo + (size_t)mTile * 128 * DIM;
    const __nv_bfloat16* BhG = Whi + (size_t)nTile * 128 * DIM;
    const __nv_bfloat16* BlG = Wlo + (size_t)nTile * 128 * DIM;

    const int fR = tid >> 2;      // 0..63 (row, two iters: +0, +64)
    const int fQ = tid & 3;       // 16B chunk within 64B row

    float acc[4][4][4];
#pragma unroll
    for (int mt = 0; mt < 4; ++mt)
#pragma unroll
        for (int nt = 0; nt < 4; ++nt)
#pragma unroll
            for (int r = 0; r < 4; ++r) acc[mt][nt][r] = 0.f;

    auto fillStage = [&](int st, int k0) {
        const uint32_t base = sb + st * STAGE_B;
#pragma unroll
        for (int i = 0; i < 2; ++i) {
            const int r = fR + i * 64;
            const uint32_t off = (uint32_t)(r * 64 + ((fQ ^ (r & 3)) << 4));
            const size_t go = (size_t)r * DIM + k0 + fQ * 8;
            cp_async16(base + off,         AhG + go);
            cp_async16(base + 8192 + off,  AlG + go);
            cp_async16(base + 16384 + off, BhG + go);
            cp_async16(base + 24576 + off, BlG + go);
        }
        CP_COMMIT();
    };

    // prologue: stages 0, 1 in flight
    fillStage(0, 0);
    fillStage(1, BKC);

    const int l7 = lane & 7, l8 = (lane >> 3) & 1, l16 = lane >> 4;

    for (int c = 0; c < NCH; ++c) {
        if (c + 1 < NCH) { CP_WAIT1(); } else { CP_WAIT0(); }
        __syncthreads();
        if (c + 2 < NCH) fillStage((c + 2) % NSTAGE, (c + 2) * BKC);

        const uint32_t sA = sb + (c % NSTAGE) * STAGE_B;
        const uint32_t sB = sA + 16384;
#pragma unroll
        for (int ks = 0; ks < 2; ++ks) {
            uint32_t b_hi[2][4], b_lo[2][4];
#pragma unroll
            for (int bt = 0; bt < 2; ++bt) {
                const int n = wn * 32 + bt * 16 + l16 * 8 + l7;
                const int ch = (ks * 2 + l8) ^ (n & 3);
                const uint32_t off = (uint32_t)(n * 64 + (ch << 4));
                ldsm_x4(b_hi[bt], sB + off);
                ldsm_x4(b_lo[bt], sB + 8192 + off);
            }
#pragma unroll
            for (int mt = 0; mt < 4; ++mt) {
                uint32_t a_hi[4], a_lo[4];
                const int r = wm * 64 + mt * 16 + l8 * 8 + l7;
                const int ch = (ks * 2 + l16) ^ (r & 3);
                const uint32_t off = (uint32_t)(r * 64 + (ch << 4));
                ldsm_x4(a_hi, sA + off);
                ldsm_x4(a_lo, sA + 8192 + off);
#pragma unroll
                for (int bt = 0; bt < 2; ++bt) {
                    mma_bf16(acc[mt][bt * 2 + 0], a_hi, &b_hi[bt][0]);
                    mma_bf16(acc[mt][bt * 2 + 0], a_hi, &b_lo[bt][0]);
                    mma_bf16(acc[mt][bt * 2 + 0], a_lo, &b_hi[bt][0]);
                    mma_bf16(acc[mt][bt * 2 + 1], a_hi, &b_hi[bt][2]);
                    mma_bf16(acc[mt][bt * 2 + 1], a_hi, &b_lo[bt][2]);
                    mma_bf16(acc[mt][bt * 2 + 1], a_lo, &b_hi[bt][2]);
                }
            }
        }
        __syncthreads();
    }

    // ---- epilogue ----
    const int rq = lane >> 2;
    const int cq = (lane & 3) * 2;
#pragma unroll
    for (int mt = 0; mt < 4; ++mt) {
#pragma unroll
        for (int h = 0; h < 2; ++h) {
            const int row = mTile * 128 + wm * 64 + mt * 16 + h * 8 + rq;
            const float* curRow = cur + (size_t)row * DIM;
#pragma unroll
            for (int nt = 0; nt < 4; ++nt) {
                const int col = nTile * 128 + wn * 32 + nt * 8 + cq;
                float v0 = acc[mt][nt][h * 2 + 0];
                float v1 = acc[mt][nt][h * 2 + 1];
                float2 b2 = *(const float2*)(bias + col);
                float2 c2 = *(const float2*)(curRow + col);
                if (MODE == 0) {
                    float2 t2 = *(const float2*)(td + col);
                    float s0 = (1.f / (1.f + expf(-(v0 + b2.x)))) * c2.x * t2.x;
                    float s1 = (1.f / (1.f + expf(-(v1 + b2.y)))) * c2.y * t2.y;
                    uint32_t hi, lo;
                    split2(s0, s1, hi, lo);
                    *(uint32_t*)(outHi + (size_t)row * DIM + col) = hi;
                    *(uint32_t*)(outLo + (size_t)row * DIM + col) = lo;
                } else {
                    float2 o;
                    o.x = v0 + b2.x + c2.x;
                    o.y = v1 + b2.y + c2.y;
                    *(float2*)(outF + (size_t)row * DIM + col) = o;
                }
            }
        }
    }
}

// ---------------- LayerNorm over last dim (row = token); optional split output ----------------
__global__ __launch_bounds__(256)
void ln_kernel(const float* __restrict__ Y, const float* __restrict__ g,
               const float* __restrict__ beta, float* __restrict__ out,
               __nv_bfloat16* __restrict__ outHi, __nv_bfloat16* __restrict__ outLo)
{
    const size_t row = blockIdx.x;
    const int tid = threadIdx.x;
    float4 v = ((const float4*)(Y + row * DIM))[tid];

    float s = v.x + v.y + v.z + v.w;
    float q = fmaf(v.x, v.x, fmaf(v.y, v.y, fmaf(v.z, v.z, v.w * v.w)));
#pragma unroll
    for (int off = 16; off; off >>= 1) {
        s += __shfl_xor_sync(0xffffffffu, s, off);
        q += __shfl_xor_sync(0xffffffffu, q, off);
    }
    __shared__ float ss[8], qq[8], mv[2];
    if ((tid & 31) == 0) { ss[tid >> 5] = s; qq[tid >> 5] = q; }
    __syncthreads();
    if (tid == 0) {
        float S = 0.f, Q = 0.f;
#pragma unroll
        for (int w = 0; w < 8; ++w) { S += ss[w]; Q += qq[w]; }
        float mean = S * (1.0f / DIM);
        float var  = Q * (1.0f / DIM) - mean * mean;
        mv[0] = mean;
        mv[1] = rsqrtf(var + LN_EPS);
    }
    __syncthreads();
    const float mean = mv[0], rstd = mv[1];
    float4 g4 = ((const float4*)g)[tid];
    float4 b4 = ((const float4*)beta)[tid];
    float4 o;
    o.x = (v.x - mean) * rstd * g4.x + b4.x;
    o.y = (v.y - mean) * rstd * g4.y + b4.y;
    o.z = (v.z - mean) * rstd * g4.z + b4.z;
    o.w = (v.w - mean) * rstd * g4.w + b4.w;
    ((float4*)(out + row * DIM))[tid] = o;
    if (outHi) {
        unsigned long long hi, lo;
        split4(o, hi, lo);
        ((unsigned long long*)(outHi + row * DIM))[tid] = hi;
        ((unsigned long long*)(outLo + row * DIM))[tid] = lo;
    }
}

// ---------------- MoLE ----------------
__device__ __forceinline__ float gelu_exact(float x)
{
    return 0.5f * x * (1.f + erff(x * 0.70710678118654752440f));
}

__global__ __launch_bounds__(128)
void mole_kernel(const float* __restrict__ Z, const float* __restrict__ gate_W,
                 const float* __restrict__ gate_b, const float* __restrict__ lora_A,
                 const float* __restrict__ lora_B, float* __restrict__ pred,
                 float* __restrict__ gp)
{
    const size_t t = blockIdx.x;
    const int tid = threadIdx.x;
    const int lane = tid & 31, wid = tid >> 5;

    __shared__ float xs[DIM];
    __shared__ float lred[4][4];
    __shared__ float hred[4][32];
    __shared__ float hs[32];
    __shared__ int   eidx[2];

    ((float4*)xs)[tid]       = ((const float4*)(Z + t * DIM))[tid];
    ((float4*)xs)[tid + 128] = ((const float4*)(Z + t * DIM))[tid + 128];
    __syncthreads();

    float4 la = {0.f, 0.f, 0.f, 0.f};
    for (int d = tid; d < DIM; d += 128) {
        float xv = xs[d];
        float4 w = *(const float4*)(gate_W + d * NEXP);
        la.x = fmaf(xv, w.x, la.x);
        la.y = fmaf(xv, w.y, la.y);
        la.z = fmaf(xv, w.z, la.z);
        la.w = fmaf(xv, w.w, la.w);
    }
#pragma unroll
    for (int off = 16; off; off >>= 1) {
        la.x += __shfl_xor_sync(0xffffffffu, la.x, off);
        la.y += __shfl_xor_sync(0xffffffffu, la.y, off);
        la.z += __shfl_xor_sync(0xffffffffu, la.z, off);
        la.w += __shfl_xor_sync(0xffffffffu, la.w, off);
    }
    if (lane == 0) {
        lred[wid][0] = la.x; lred[wid][1] = la.y;
        lred[wid][2] = la.z; lred[wid][3] = la.w;
    }
    __syncthreads();

    if (tid == 0) {
        float lg[NEXP];
#pragma unroll
        for (int e = 0; e < NEXP; ++e)
            lg[e] = lred[0][e] + lred[1][e] + lred[2][e] + lred[3][e] + gate_b[e];
        float m = lg[0];
#pragma unroll
        for (int e = 1; e < NEXP; ++e) m = fmaxf(m, lg[e]);
        float p[NEXP], s = 0.f;
#pragma unroll
        for (int e = 0; e < NEXP; ++e) { p[e] = expf(lg[e] - m); s += p[e]; }
        float inv = 1.f / s;
#pragma unroll
        for (int e = 0; e < NEXP; ++e) gp[t * NEXP + e] = p[e] * inv;
        int i0 = 0;
#pragma unroll
        for (int e = 1; e < NEXP; ++e) if (lg[e] > lg[i0]) i0 = e;
        int i1 = -1;
#pragma unroll
        for (int e = 0; e < NEXP; ++e)
            if (e != i0 && (i1 < 0 || lg[e] > lg[i1])) i1 = e;
        eidx[0] = i0; eidx[1] = i1;
    }
    __syncthreads();

    const int e0 = eidx[0], e1 = eidx[1];
    const float* A0 = lora_A + (size_t)e0 * DIM * RRANK;
    const float* A1 = lora_A + (size_t)e1 * DIM * RRANK;

    float hacc[32];
#pragma unroll
    for (int i = 0; i < 32; ++i) hacc[i] = 0.f;
    for (int d = tid; d < DIM; d += 128) {
        float xv = xs[d];
        const float4* a0 = (const float4*)(A0 + d * RRANK);
        const float4* a1 = (const float4*)(A1 + d * RRANK);
#pragma unroll
        for (int q = 0; q < 4; ++q) {
            float4 a = a0[q];
            hacc[q * 4 + 0] = fmaf(xv, a.x, hacc[q * 4 + 0]);
            hacc[q * 4 + 1] = fmaf(xv, a.y, hacc[q * 4 + 1]);
            hacc[q * 4 + 2] = fmaf(xv, a.z, hacc[q * 4 + 2]);
            hacc[q * 4 + 3] = fmaf(xv, a.w, hacc[q * 4 + 3]);
        }
#pragma unroll
        for (int q = 0; q < 4; ++q) {
            float4 a = a1[q];
            hacc[16 + q * 4 + 0] = fmaf(xv, a.x, hacc[16 + q * 4 + 0]);
            hacc[16 + q * 4 + 1] = fmaf(xv, a.y, hacc[16 + q * 4 + 1]);
            hacc[16 + q * 4 + 2] = fmaf(xv, a.z, hacc[16 + q * 4 + 2]);
            hacc[16 + q * 4 + 3] = fmaf(xv, a.w, hacc[16 + q * 4 + 3]);
        }
    }
#pragma unroll
    for (int off = 16; off; off >>= 1)
#pragma unroll
        for (int i = 0; i < 32; ++i)
            hacc[i] += __shfl_xor_sync(0xffffffffu, hacc[i], off);
    if (lane == 0)
#pragma unroll
        for (int i = 0; i < 32; ++i) hred[wid][i] = hacc[i];
    __syncthreads();
    if (tid < 32) {
        float v = hred[0][tid] + hred[1][tid] + hred[2][tid] + hred[3][tid];
        hs[tid] = gelu_exact(v);
    }
    __syncthreads();

    const float* B0 = lora_B + (size_t)e0 * RRANK * DIM;
    const float* B1 = lora_B + (size_t)e1 * RRANK * DIM;
#pragma unroll
    for (int i = 0; i < 8; ++i) {
        const int d = tid + i * 128;
        float acc = 0.f;
#pragma unroll
        for (int r = 0; r < RRANK; ++r) {
            acc = fmaf(hs[r],      B0[r * DIM + d], acc);
            acc = fmaf(hs[16 + r], B1[r * DIM + d], acc);
        }
        pred[t * DIM + d] = acc;
    }
}

// ---------------- host orchestration ----------------
static void run_stack(const float* x, const float* Wi, const float* bi, const float* td,
                      const float* Wo, const float* bo, const float* g, const float* beta,
                      float* bufY, float* bufA, float* finalOut,
                      __nv_bfloat16* zhi, __nv_bfloat16* zlo,
                      __nv_bfloat16* shi, __nv_bfloat16* slo,
                      __nv_bfloat16* whi, __nv_bfloat16* wlo)
{
    dim3 ggrid(DIM / 128, T_TOK / 128);
    dim3 wgrid(DIM / 32, DIM / 32);

    // split stack input once
    xsplit_kernel<<<(T_TOK * DIM / 4) / 256, 256>>>(x, zhi, zlo);

    const float* cur = x;
    for (int l = 0; l < NL; ++l) {
        wsplit_kernel<<<wgrid, 256>>>(Wi + (size_t)l * DIM * DIM, whi, wlo);
        gemm_mma<0><<<ggrid, 256, SMEMSZ>>>(zhi, zlo, whi, wlo, bi + l * DIM,
                                            cur, td + l * DIM, nullptr, shi, slo);
        wsplit_kernel<<<wgrid, 256>>>(Wo + (size_t)l * DIM * DIM, whi, wlo);
        gemm_mma<1><<<ggrid, 256, SMEMSZ>>>(shi, slo, whi, wlo, bo + l * DIM,
                                            cur, nullptr, bufY, nullptr, nullptr);
        const bool last = (l == NL - 1);
        float* lnout = last ? finalOut : bufA;
        ln_kernel<<<T_TOK, 256>>>(bufY, g + l * DIM, beta + l * DIM, lnout,
                                  last ? nullptr : zhi, last ? nullptr : zlo);
        cur = bufA;
    }
}

extern "C" void kernel_launch(void* const* d_in, const int* in_sizes, int n_in,
                              void* d_out, int out_size)
{
    const float* x_context = (const float*)d_in[0];
    const float* x_target  = (const float*)d_in[1];
    const float* enc_Wi   = (const float*)d_in[2];
    const float* enc_bi   = (const float*)d_in[3];
    const float* enc_td   = (const float*)d_in[4];
    const float* enc_Wo   = (const float*)d_in[5];
    const float* enc_bo   = (const float*)d_in[6];
    const float* enc_g    = (const float*)d_in[7];
    const float* enc_beta = (const float*)d_in[8];
    const float* tgt_Wi   = (const float*)d_in[9];
    const float* tgt_bi   = (const float*)d_in[10];
    const float* tgt_td   = (const float*)d_in[11];
    const float* tgt_Wo   = (const float*)d_in[12];
    const float* tgt_bo   = (const float*)d_in[13];
    const float* tgt_g    = (const float*)d_in[14];
    const float* tgt_beta = (const float*)d_in[15];
    const float* gate_W   = (const float*)d_in[16];
    const float* gate_b   = (const float*)d_in[17];
    const float* lora_A   = (const float*)d_in[18];
    const float* lora_B   = (const float*)d_in[19];

    float *bufY, *bufA;
    __nv_bfloat16 *zhi, *zlo, *shi, *slo, *whi, *wlo;
    cudaGetSymbolAddress((void**)&bufY, g_bufY);
    cudaGetSymbolAddress((void**)&bufA, g_bufA);
    cudaGetSymbolAddress((void**)&zhi, g_Zhi);
    cudaGetSymbolAddress((void**)&zlo, g_Zlo);
    cudaGetSymbolAddress((void**)&shi, g_Shi);
    cudaGetSymbolAddress((void**)&slo, g_Slo);
    cudaGetSymbolAddress((void**)&whi, g_Whi);
    cudaGetSymbolAddress((void**)&wlo, g_Wlo);

    cudaFuncSetAttribute(gemm_mma<0>, cudaFuncAttributeMaxDynamicSharedMemorySize, SMEMSZ);
    cudaFuncSetAttribute(gemm_mma<1>, cudaFuncAttributeMaxDynamicSharedMemorySize, SMEMSZ);

    float* out  = (float*)d_out;
    float* pred = out;                                   // [T, D]
    float* gp   = out + (size_t)T_TOK * DIM;             // [T, E]
    float* ztg  = gp + (size_t)T_TOK * NEXP;             // [T, D]

    // encoder stack -> z_context in bufA
    run_stack(x_context, enc_Wi, enc_bi, enc_td, enc_Wo, enc_bo, enc_g, enc_beta,
              bufY, bufA, bufA, zhi, zlo, shi, slo, whi, wlo);

    // MoLE on z_context -> pred_z + gate_probs
    mole_kernel<<<T_TOK, 128>>>(bufA, gate_W, gate_b, lora_A, lora_B, pred, gp);

    // target stack -> z_target directly into d_out
    run_stack(x_target, tgt_Wi, tgt_bi, tgt_td, tgt_Wo, tgt_bo, tgt_g, tgt_beta,
              bufY, bufA, ztg, zhi, zlo, shi, slo, whi, wlo);
}

// round 15
// speedup vs baseline: 2.3883x; 1.0211x over previous
#include <cuda_runtime.h>
#include <cuda_bf16.h>
#include <math.h>
#include <stdint.h>

#define DIM   1024
#define T_TOK 16384
#define NL    3
#define NEXP  4
#define RRANK 16
#define LN_EPS 1e-5f

#define T2 (2 * T_TOK)     // both stacks batched

// ---------------- scratch (no allocations allowed) ----------------
__device__ float g_bufY[(size_t)T2 * DIM];               // pre-LN Y (fp32), batched
__device__ float g_bufA[(size_t)T2 * DIM];               // post-LN activation, batched
__device__ __nv_bfloat16 g_Zhi[(size_t)T2 * DIM];        // gemm<0> A operand split
__device__ __nv_bfloat16 g_Zlo[(size_t)T2 * DIM];
__device__ __nv_bfloat16 g_Shi[(size_t)T2 * DIM];        // liquid state S split
__device__ __nv_bfloat16 g_Slo[(size_t)T2 * DIM];
// 12 weight slots: slot = stk*6 + l*2 + which(0=Wi,1=Wo); each W^T [N][K]
__device__ __nv_bfloat16 g_WhiAll[(size_t)12 * DIM * DIM];
__device__ __nv_bfloat16 g_WloAll[(size_t)12 * DIM * DIM];

// ================= PTX helpers (base compute_103 only) =================
__device__ __forceinline__ uint32_t smem_u32(const void* p) {
    uint32_t a;
    asm("{ .reg .u64 t; cvta.to.shared.u64 t, %1; cvt.u32.u64 %0, t; }" : "=r"(a) : "l"(p));
    return a;
}

__device__ __forceinline__ void cp_async16(uint32_t dst, const void* src) {
    asm volatile("cp.async.cg.shared.global [%0], [%1], 16;" :: "r"(dst), "l"(src));
}
#define CP_COMMIT() asm volatile("cp.async.commit_group;" ::: "memory")
#define CP_WAIT0()  asm volatile("cp.async.wait_group 0;" ::: "memory")
#define CP_WAIT1()  asm volatile("cp.async.wait_group 1;" ::: "memory")

__device__ __forceinline__ void ldsm_x4(uint32_t* r, uint32_t addr) {
    asm volatile("ldmatrix.sync.aligned.m8n8.x4.shared.b16 {%0,%1,%2,%3}, [%4];"
                 : "=r"(r[0]), "=r"(r[1]), "=r"(r[2]), "=r"(r[3]) : "r"(addr));
}

__device__ __forceinline__ void mma_bf16(float* d, const uint32_t* a, const uint32_t* b) {
    asm volatile(
        "mma.sync.aligned.m16n8k16.row.col.f32.bf16.bf16.f32 "
        "{%0,%1,%2,%3}, {%4,%5,%6,%7}, {%8,%9}, {%0,%1,%2,%3};"
        : "+f"(d[0]), "+f"(d[1]), "+f"(d[2]), "+f"(d[3])
        : "r"(a[0]), "r"(a[1]), "r"(a[2]), "r"(a[3]), "r"(b[0]), "r"(b[1]));
}

// split a float4 into packed-4 hi bf16 and packed-4 lo bf16 (8 bytes each)
__device__ __forceinline__ void split4(float4 v, unsigned long long& hi, unsigned long long& lo) {
    __nv_bfloat162 h0 = __float22bfloat162_rn(make_float2(v.x, v.y));
    __nv_bfloat162 h1 = __float22bfloat162_rn(make_float2(v.z, v.w));
    float2 f0 = __bfloat1622float2(h0);
    float2 f1 = __bfloat1622float2(h1);
    __nv_bfloat162 l0 = __float22bfloat162_rn(make_float2(v.x - f0.x, v.y - f0.y));
    __nv_bfloat162 l1 = __float22bfloat162_rn(make_float2(v.z - f1.x, v.w - f1.y));
    uint32_t uh0 = *reinterpret_cast<uint32_t*>(&h0);
    uint32_t uh1 = *reinterpret_cast<uint32_t*>(&h1);
    uint32_t ul0 = *reinterpret_cast<uint32_t*>(&l0);
    uint32_t ul1 = *reinterpret_cast<uint32_t*>(&l1);
    hi = (unsigned long long)uh0 | ((unsigned long long)uh1 << 32);
    lo = (unsigned long long)ul0 | ((unsigned long long)ul1 << 32);
}

__device__ __forceinline__ void split2(float a, float b, uint32_t& hi, uint32_t& lo) {
    __nv_bfloat162 h = __float22bfloat162_rn(make_float2(a, b));
    float2 f = __bfloat1622float2(h);
    __nv_bfloat162 l = __float22bfloat162_rn(make_float2(a - f.x, b - f.y));
    hi = *reinterpret_cast<uint32_t*>(&h);
    lo = *reinterpret_cast<uint32_t*>(&l);
}

// ---------------- x split: both stacks in one launch (z = stack) ----------------
__global__ __launch_bounds__(256)
void xsplit_kernel(const float* __restrict__ XE, const float* __restrict__ XT,
                   __nv_bfloat16* __restrict__ Xhi, __nv_bfloat16* __restrict__ Xlo)
{
    const int stk = blockIdx.y;
    const float* X = stk ? XT : XE;
    const size_t idx = (size_t)blockIdx.x * 256 + threadIdx.x;               // float4 idx
    const size_t gout = (size_t)stk * (T_TOK * DIM / 4) + idx;
    float4 v = ((const float4*)X)[idx];
    unsigned long long hi, lo;
    split4(v, hi, lo);
    ((unsigned long long*)Xhi)[gout] = hi;
    ((unsigned long long*)Xlo)[gout] = lo;
}

// ---------------- all 12 weight transpose+splits in ONE launch ----------------
// slot s (blockIdx.z): stk = s/6, l = (s%6)/2, which = s%2
__global__ __launch_bounds__(256)
void wsplit_all_kernel(const float* __restrict__ encWi, const float* __restrict__ encWo,
                       const float* __restrict__ tgtWi, const float* __restrict__ tgtWo,
                       __nv_bfloat16* __restrict__ WhiAll, __nv_bfloat16* __restrict__ WloAll)
{
    __shared__ float tile[32][33];
    const int s = blockIdx.z;
    const int stk = s / 6, rem = s % 6, l = rem >> 1, which = rem & 1;
    const float* Wbase = stk ? (which ? tgtWo : tgtWi) : (which ? encWo : encWi);
    const float* W = Wbase + (size_t)l * DIM * DIM;
    __nv_bfloat16* Whi = WhiAll + (size_t)s * DIM * DIM;
    __nv_bfloat16* Wlo = WloAll + (size_t)s * DIM * DIM;

    const int n0 = blockIdx.x * 32, k0 = blockIdx.y * 32;
    const int tx = threadIdx.x & 31, ty = threadIdx.x >> 5;
#pragma unroll
    for (int i = 0; i < 32; i += 8)
        tile[ty + i][tx] = W[(size_t)(k0 + ty + i) * DIM + n0 + tx];
    __syncthreads();
#pragma unroll
    for (int i = 0; i < 32; i += 8) {
        float v = tile[tx][ty + i];             // W[k0+tx][n0+ty+i]
        __nv_bfloat16 h = __float2bfloat16(v);
        const size_t o = (size_t)(n0 + ty + i) * DIM + k0 + tx;
        Whi[o] = h;
        Wlo[o] = __float2bfloat16(v - __bfloat162float(h));
    }
}

// ---------------- HMMA bf16x3 GEMM, both stacks batched (z = stack) ----------------
// MODE 0: s = sigmoid(acc + bias[c]) * cur[r,c] * td[c]  -> split bf16 (outHi/outLo, batched)
// MODE 1: out = acc + bias[c] + cur[r,c]                 -> fp32 (outF, batched)
#define BKC      32
#define NCH      (DIM / BKC)     // 32
#define STAGE_B  32768
#define NSTAGE   3
#define SMEMSZ   (NSTAGE * STAGE_B)

template <int MODE>
__global__ __launch_bounds__(256, 2)
void gemm_mma(const __nv_bfloat16* __restrict__ Ahi, const __nv_bfloat16* __restrict__ Alo,
              const __nv_bfloat16* __restrict__ WhiAll, const __nv_bfloat16* __restrict__ WloAll,
              int wslot,
              const float* __restrict__ biasE, const float* __restrict__ biasT,
              const float* __restrict__ curE, const float* __restrict__ curT,
              const float* __restrict__ tdE, const float* __restrict__ tdT,
              float* __restrict__ outF,
              __nv_bfloat16* __restrict__ outHi, __nv_bfloat16* __restrict__ outLo)
{
    extern __shared__ char smem[];
    const uint32_t sb = smem_u32(smem);
    const int tid  = threadIdx.x;
    const int wid  = tid >> 5, lane = tid & 31;
    const int mTile = blockIdx.y, nTile = blockIdx.x;
    const int stk = blockIdx.z;
    const int wm = wid >> 2;      // 0..1
    const int wn = wid & 3;       // 0..3

    const size_t rowBaseG = (size_t)stk * T_TOK + (size_t)mTile * 128;   // batched A/out row
    const __nv_bfloat16* AhG = Ahi + rowBaseG * DIM;
    const __nv_bfloat16* AlG = Alo + rowBaseG * DIM;
    const size_t wOff = ((size_t)(wslot + stk * 6)) * DIM * DIM + (size_t)nTile * 128 * DIM;
    const __nv_bfloat16* BhG = WhiAll + wOff;
    const __nv_bfloat16* BlG = WloAll + wOff;

    const float* bias = stk ? biasT : biasE;
    const float* cur  = stk ? curT  : curE;     // indexed by LOCAL row
    const float* td   = stk ? tdT   : tdE;

    const int fR = tid >> 2;      // 0..63
    const int fQ = tid & 3;       // 16B chunk within 64B row

    float acc[4][4][4];
#pragma unroll
    for (int mt = 0; mt < 4; ++mt)
#pragma unroll
        for (int nt = 0; nt < 4; ++nt)
#pragma unroll
            for (int r = 0; r < 4; ++r) acc[mt][nt][r] = 0.f;

    auto fillStage = [&](int st, int k0) {
        const uint32_t base = sb + st * STAGE_B;
#pragma unroll
        for (int i = 0; i < 2; ++i) {
            const int r = fR + i * 64;
            const uint32_t off = (uint32_t)(r * 64 + ((fQ ^ (r & 3)) << 4));
            const size_t go = (size_t)r * DIM + k0 + fQ * 8;
            cp_async16(base + off,         AhG + go);
            cp_async16(base + 8192 + off,  AlG + go);
            cp_async16(base + 16384 + off, BhG + go);
            cp_async16(base + 24576 + off, BlG + go);
        }
        CP_COMMIT();
    };

    fillStage(0, 0);
    fillStage(1, BKC);

    const int l7 = lane & 7, l8 = (lane >> 3) & 1, l16 = lane >> 4;

    for (int c = 0; c < NCH; ++c) {
        if (c + 1 < NCH) { CP_WAIT1(); } else { CP_WAIT0(); }
        __syncthreads();
        // Safe without a trailing sync: every warp passed this barrier only after
        // finishing chunk c-1's ldsm (program order), and stage (c+2)%3 was last
        // read during chunk c-1.
        if (c + 2 < NCH) fillStage((c + 2) % NSTAGE, (c + 2) * BKC);

        const uint32_t sA = sb + (c % NSTAGE) * STAGE_B;
        const uint32_t sB = sA + 16384;
#pragma unroll
        for (int ks = 0; ks < 2; ++ks) {
            uint32_t b_hi[2][4], b_lo[2][4];
#pragma unroll
            for (int bt = 0; bt < 2; ++bt) {
                const int n = wn * 32 + bt * 16 + l16 * 8 + l7;
                const int ch = (ks * 2 + l8) ^ (n & 3);
                const uint32_t off = (uint32_t)(n * 64 + (ch << 4));
                ldsm_x4(b_hi[bt], sB + off);
                ldsm_x4(b_lo[bt], sB + 8192 + off);
            }
#pragma unroll
            for (int mt = 0; mt < 4; ++mt) {
                uint32_t a_hi[4], a_lo[4];
                const int r = wm * 64 + mt * 16 + l8 * 8 + l7;
                const int ch = (ks * 2 + l16) ^ (r & 3);
                const uint32_t off = (uint32_t)(r * 64 + (ch << 4));
                ldsm_x4(a_hi, sA + off);
                ldsm_x4(a_lo, sA + 8192 + off);
#pragma unroll
                for (int bt = 0; bt < 2; ++bt) {
                    mma_bf16(acc[mt][bt * 2 + 0], a_hi, &b_hi[bt][0]);
                    mma_bf16(acc[mt][bt * 2 + 0], a_hi, &b_lo[bt][0]);
                    mma_bf16(acc[mt][bt * 2 + 0], a_lo, &b_hi[bt][0]);
                    mma_bf16(acc[mt][bt * 2 + 1], a_hi, &b_hi[bt][2]);
                    mma_bf16(acc[mt][bt * 2 + 1], a_hi, &b_lo[bt][2]);
                    mma_bf16(acc[mt][bt * 2 + 1], a_lo, &b_hi[bt][2]);
                }
            }
        }
    }

    // ---- epilogue ----
    const int rq = lane >> 2;
    const int cq = (lane & 3) * 2;
#pragma unroll
    for (int mt = 0; mt < 4; ++mt) {
#pragma unroll
        for (int h = 0; h < 2; ++h) {
            const int lrow = mTile * 128 + wm * 64 + mt * 16 + h * 8 + rq;   // local row
            const size_t grow = (size_t)stk * T_TOK + lrow;                  // batched row
            const float* curRow = cur + (size_t)lrow * DIM;
#pragma unroll
            for (int nt = 0; nt < 4; ++nt) {
                const int col = nTile * 128 + wn * 32 + nt * 8 + cq;
                float v0 = acc[mt][nt][h * 2 + 0];
                float v1 = acc[mt][nt][h * 2 + 1];
                float2 b2 = *(const float2*)(bias + col);
                float2 c2 = *(const float2*)(curRow + col);
                if (MODE == 0) {
                    float2 t2 = *(const float2*)(td + col);
                    float s0 = (1.f / (1.f + expf(-(v0 + b2.x)))) * c2.x * t2.x;
                    float s1 = (1.f / (1.f + expf(-(v1 + b2.y)))) * c2.y * t2.y;
                    uint32_t hi, lo;
                    split2(s0, s1, hi, lo);
                    *(uint32_t*)(outHi + grow * DIM + col) = hi;
                    *(uint32_t*)(outLo + grow * DIM + col) = lo;
                } else {
                    float2 o;
                    o.x = v0 + b2.x + c2.x;
                    o.y = v1 + b2.y + c2.y;
                    *(float2*)(outF + grow * DIM + col) = o;
                }
            }
        }
    }
}

// ---------------- LayerNorm, both stacks batched; optional split output ----------------
__global__ __launch_bounds__(256)
void ln_kernel(const float* __restrict__ Y,
               const float* __restrict__ gE, const float* __restrict__ betaE,
               const float* __restrict__ gT, const float* __restrict__ betaT,
               float* __restrict__ outE, float* __restrict__ outT,
               __nv_bfloat16* __restrict__ outHi, __nv_bfloat16* __restrict__ outLo)
{
    const size_t row = blockIdx.x;                 // 0..2T-1
    const int stk = (int)(row >> 14);              // T_TOK = 16384
    const size_t lrow = row & (T_TOK - 1);
    const int tid = threadIdx.x;
    float4 v = ((const float4*)(Y + row * DIM))[tid];

    float s = v.x + v.y + v.z + v.w;
    float q = fmaf(v.x, v.x, fmaf(v.y, v.y, fmaf(v.z, v.z, v.w * v.w)));
#pragma unroll
    for (int off = 16; off; off >>= 1) {
        s += __shfl_xor_sync(0xffffffffu, s, off);
        q += __shfl_xor_sync(0xffffffffu, q, off);
    }
    __shared__ float ss[8], qq[8], mv[2];
    if ((tid & 31) == 0) { ss[tid >> 5] = s; qq[tid >> 5] = q; }
    __syncthreads();
    if (tid == 0) {
        float S = 0.f, Q = 0.f;
#pragma unroll
        for (int w = 0; w < 8; ++w) { S += ss[w]; Q += qq[w]; }
        float mean = S * (1.0f / DIM);
        float var  = Q * (1.0f / DIM) - mean * mean;
        mv[0] = mean;
        mv[1] = rsqrtf(var + LN_EPS);
    }
    __syncthreads();
    const float mean = mv[0], rstd = mv[1];
    const float* g    = stk ? gT    : gE;
    const float* beta = stk ? betaT : betaE;
    float4 g4 = ((const float4*)g)[tid];
    float4 b4 = ((const float4*)beta)[tid];
    float4 o;
    o.x = (v.x - mean) * rstd * g4.x + b4.x;
    o.y = (v.y - mean) * rstd * g4.y + b4.y;
    o.z = (v.z - mean) * rstd * g4.z + b4.z;
    o.w = (v.w - mean) * rstd * g4.w + b4.w;
    float* out = stk ? outT : outE;
    ((float4*)(out + lrow * DIM))[tid] = o;
    if (outHi) {
        unsigned long long hi, lo;
        split4(o, hi, lo);
        ((unsigned long long*)(outHi + row * DIM))[tid] = hi;
        ((unsigned long long*)(outLo + row * DIM))[tid] = lo;
    }
}

// ---------------- MoLE ----------------
__device__ __forceinline__ float gelu_exact(float x)
{
    return 0.5f * x * (1.f + erff(x * 0.70710678118654752440f));
}

__global__ __launch_bounds__(128)
void mole_kernel(const float* __restrict__ Z, const float* __restrict__ gate_W,
                 const float* __restrict__ gate_b, const float* __restrict__ lora_A,
                 const float* __restrict__ lora_B, float* __restrict__ pred,
                 float* __restrict__ gp)
{
    const size_t t = blockIdx.x;
    const int tid = threadIdx.x;
    const int lane = tid & 31, wid = tid >> 5;

    __shared__ float xs[DIM];
    __shared__ float lred[4][4];
    __shared__ float hred[4][32];
    __shared__ float hs[32];
    __shared__ int   eidx[2];

    ((float4*)xs)[tid]       = ((const float4*)(Z + t * DIM))[tid];
    ((float4*)xs)[tid + 128] = ((const float4*)(Z + t * DIM))[tid + 128];
    __syncthreads();

    float4 la = {0.f, 0.f, 0.f, 0.f};
    for (int d = tid; d < DIM; d += 128) {
        float xv = xs[d];
        float4 w = *(const float4*)(gate_W + d * NEXP);
        la.x = fmaf(xv, w.x, la.x);
        la.y = fmaf(xv, w.y, la.y);
        la.z = fmaf(xv, w.z, la.z);
        la.w = fmaf(xv, w.w, la.w);
    }
#pragma unroll
    for (int off = 16; off; off >>= 1) {
        la.x += __shfl_xor_sync(0xffffffffu, la.x, off);
        la.y += __shfl_xor_sync(0xffffffffu, la.y, off);
        la.z += __shfl_xor_sync(0xffffffffu, la.z, off);
        la.w += __shfl_xor_sync(0xffffffffu, la.w, off);
    }
    if (lane == 0) {
        lred[wid][0] = la.x; lred[wid][1] = la.y;
        lred[wid][2] = la.z; lred[wid][3] = la.w;
    }
    __syncthreads();

    if (tid == 0) {
        float lg[NEXP];
#pragma unroll
        for (int e = 0; e < NEXP; ++e)
            lg[e] = lred[0][e] + lred[1][e] + lred[2][e] + lred[3][e] + gate_b[e];
        float m = lg[0];
#pragma unroll
        for (int e = 1; e < NEXP; ++e) m = fmaxf(m, lg[e]);
        float p[NEXP], s = 0.f;
#pragma unroll
        for (int e = 0; e < NEXP; ++e) { p[e] = expf(lg[e] - m); s += p[e]; }
        float inv = 1.f / s;
#pragma unroll
        for (int e = 0; e < NEXP; ++e) gp[t * NEXP + e] = p[e] * inv;
        int i0 = 0;
#pragma unroll
        for (int e = 1; e < NEXP; ++e) if (lg[e] > lg[i0]) i0 = e;
        int i1 = -1;
#pragma unroll
        for (int e = 0; e < NEXP; ++e)
            if (e != i0 && (i1 < 0 || lg[e] > lg[i1])) i1 = e;
        eidx[0] = i0; eidx[1] = i1;
    }
    __syncthreads();

    const int e0 = eidx[0], e1 = eidx[1];
    const float* A0 = lora_A + (size_t)e0 * DIM * RRANK;
    const float* A1 = lora_A + (size_t)e1 * DIM * RRANK;

    float hacc[32];
#pragma unroll
    for (int i = 0; i < 32; ++i) hacc[i] = 0.f;
    for (int d = tid; d < DIM; d += 128) {
        float xv = xs[d];
        const float4* a0 = (const float4*)(A0 + d * RRANK);
        const float4* a1 = (const float4*)(A1 + d * RRANK);
#pragma unroll
        for (int q = 0; q < 4; ++q) {
            float4 a = a0[q];
            hacc[q * 4 + 0] = fmaf(xv, a.x, hacc[q * 4 + 0]);
            hacc[q * 4 + 1] = fmaf(xv, a.y, hacc[q * 4 + 1]);
            hacc[q * 4 + 2] = fmaf(xv, a.z, hacc[q * 4 + 2]);
            hacc[q * 4 + 3] = fmaf(xv, a.w, hacc[q * 4 + 3]);
        }
#pragma unroll
        for (int q = 0; q < 4; ++q) {
            float4 a = a1[q];
            hacc[16 + q * 4 + 0] = fmaf(xv, a.x, hacc[16 + q * 4 + 0]);
            hacc[16 + q * 4 + 1] = fmaf(xv, a.y, hacc[16 + q * 4 + 1]);
            hacc[16 + q * 4 + 2] = fmaf(xv, a.z, hacc[16 + q * 4 + 2]);
            hacc[16 + q * 4 + 3] = fmaf(xv, a.w, hacc[16 + q * 4 + 3]);
        }
    }
#pragma unroll
    for (int off = 16; off; off >>= 1)
#pragma unroll
        for (int i = 0; i < 32; ++i)
            hacc[i] += __shfl_xor_sync(0xffffffffu, hacc[i], off);
    if (lane == 0)
#pragma unroll
        for (int i = 0; i < 32; ++i) hred[wid][i] = hacc[i];
    __syncthreads();
    if (tid < 32) {
        float v = hred[0][tid] + hred[1][tid] + hred[2][tid] + hred[3][tid];
        hs[tid] = gelu_exact(v);
    }
    __syncthreads();

    const float* B0 = lora_B + (size_t)e0 * RRANK * DIM;
    const float* B1 = lora_B + (size_t)e1 * RRANK * DIM;
#pragma unroll
    for (int i = 0; i < 8; ++i) {
        const int d = tid + i * 128;
        float acc = 0.f;
#pragma unroll
        for (int r = 0; r < RRANK; ++r) {
            acc = fmaf(hs[r],      B0[r * DIM + d], acc);
            acc = fmaf(hs[16 + r], B1[r * DIM + d], acc);
        }
        pred[t * DIM + d] = acc;
    }
}

// ---------------- host orchestration ----------------
extern "C" void kernel_launch(void* const* d_in, const int* in_sizes, int n_in,
                              void* d_out, int out_size)
{
    const float* x_context = (const float*)d_in[0];
    const float* x_target  = (const float*)d_in[1];
    const float* enc_Wi   = (const float*)d_in[2];
    const float* enc_bi   = (const float*)d_in[3];
    const float* enc_td   = (const float*)d_in[4];
    const float* enc_Wo   = (const float*)d_in[5];
    const float* enc_bo   = (const float*)d_in[6];
    const float* enc_g    = (const float*)d_in[7];
    const float* enc_beta = (const float*)d_in[8];
    const float* tgt_Wi   = (const float*)d_in[9];
    const float* tgt_bi   = (const float*)d_in[10];
    const float* tgt_td   = (const float*)d_in[11];
    const float* tgt_Wo   = (const float*)d_in[12];
    const float* tgt_bo   = (const float*)d_in[13];
    const float* tgt_g    = (const float*)d_in[14];
    const float* tgt_beta = (const float*)d_in[15];
    const float* gate_W   = (const float*)d_in[16];
    const float* gate_b   = (const float*)d_in[17];
    const float* lora_A   = (const float*)d_in[18];
    const float* lora_B   = (const float*)d_in[19];

    float *bufY, *bufA;
    __nv_bfloat16 *zhi, *zlo, *shi, *slo, *whiAll, *wloAll;
    cudaGetSymbolAddress((void**)&bufY, g_bufY);
    cudaGetSymbolAddress((void**)&bufA, g_bufA);
    cudaGetSymbolAddress((void**)&zhi, g_Zhi);
    cudaGetSymbolAddress((void**)&zlo, g_Zlo);
    cudaGetSymbolAddress((void**)&shi, g_Shi);
    cudaGetSymbolAddress((void**)&slo, g_Slo);
    cudaGetSymbolAddress((void**)&whiAll, g_WhiAll);
    cudaGetSymbolAddress((void**)&wloAll, g_WloAll);

    cudaFuncSetAttribute(gemm_mma<0>, cudaFuncAttributeMaxDynamicSharedMemorySize, SMEMSZ);
    cudaFuncSetAttribute(gemm_mma<1>, cudaFuncAttributeMaxDynamicSharedMemorySize, SMEMSZ);

    float* out  = (float*)d_out;
    float* pred = out;                                   // [T, D]
    float* gp   = out + (size_t)T_TOK * DIM;             // [T, E]
    float* ztg  = gp + (size_t)T_TOK * NEXP;             // [T, D]

    // all weight splits upfront, one launch
    wsplit_all_kernel<<<dim3(DIM / 32, DIM / 32, 12), 256>>>(
        enc_Wi, enc_Wo, tgt_Wi, tgt_Wo, whiAll, wloAll);
    // split both stack inputs, one launch
    xsplit_kernel<<<dim3((T_TOK * DIM / 4) / 256, 2), 256>>>(x_context, x_target, zhi, zlo);

    dim3 ggrid(DIM / 128, T_TOK / 128, 2);
    const float* curE = x_context;
    const float* curT = x_target;
    for (int l = 0; l < NL; ++l) {
        gemm_mma<0><<<ggrid, 256, SMEMSZ>>>(
            zhi, zlo, whiAll, wloAll, l * 2 + 0,
            enc_bi + l * DIM, tgt_bi + l * DIM, curE, curT,
            enc_td + l * DIM, tgt_td + l * DIM, nullptr, shi, slo);
        gemm_mma<1><<<ggrid, 256, SMEMSZ>>>(
            shi, slo, whiAll, wloAll, l * 2 + 1,
            enc_bo + l * DIM, tgt_bo + l * DIM, curE, curT,
            nullptr, nullptr, bufY, nullptr, nullptr);
        const bool last = (l == NL - 1);
        ln_kernel<<<T2, 256>>>(bufY,
                               enc_g + l * DIM, enc_beta + l * DIM,
                               tgt_g + l * DIM, tgt_beta + l * DIM,
                               bufA, last ? ztg : (bufA + (size_t)T_TOK * DIM),
                               last ? nullptr : zhi, last ? nullptr : zlo);
        curE = bufA;
        curT = bufA + (size_t)T_TOK * DIM;
    }

    // MoLE on z_context (enc half of bufA) -> pred_z + gate_probs
    mole_kernel<<<T_TOK, 128>>>(bufA, gate_W, gate_b, lora_A, lora_B, pred, gp);
}